// round 11
// baseline (speedup 1.0000x reference)
#include <cuda_runtime.h>

// Modified Bessel K1(x) on (0.1, 10.1], matching the JAX fp32 A&S reference.
// Math (R7 form, rel_err ~2e-5 vs 1e-3 budget):
//   small(x) = x*( L*P1(s) + Q'(s) ) + r          [x <= 2]
//       s = x^2, r = rcp(x), L = lg2(x)
//   large(x) = ex2( -log2e*x - 0.5*L + G(r) )     [x > 2]
// R10 = R7 flat-grid structure (V=2, TPB=256, block-interleaved addresses —
// R9 proved per-CTA chunking wrecks L2 behavior) + predicated-MUFU select:
// "@p ex2" overwrites the small result directly, killing FSETP+2xFSEL per
// pair (the alu pipe at 49% was the binder).

typedef unsigned long long ull;

__device__ __forceinline__ ull f2(float lo, float hi) {
    ull d; asm("mov.b64 %0,{%1,%2};" : "=l"(d) : "f"(lo), "f"(hi)); return d;
}
__device__ __forceinline__ ull dup(float c) { return f2(c, c); }
__device__ __forceinline__ void unpack2(ull v, float& lo, float& hi) {
    asm("mov.b64 {%0,%1},%2;" : "=f"(lo), "=f"(hi) : "l"(v));
}
__device__ __forceinline__ ull ffma2(ull a, ull b, ull c) {
    ull d; asm("fma.rn.f32x2 %0,%1,%2,%3;" : "=l"(d) : "l"(a), "l"(b), "l"(c)); return d;
}
__device__ __forceinline__ ull fmul2(ull a, ull b) {
    ull d; asm("mul.rn.f32x2 %0,%1,%2;" : "=l"(d) : "l"(a), "l"(b)); return d;
}
__device__ __forceinline__ float rcpa(float x) {
    float y; asm("rcp.approx.f32 %0,%1;" : "=f"(y) : "f"(x)); return y;
}
__device__ __forceinline__ float lg2a(float x) {
    float y; asm("lg2.approx.f32 %0,%1;" : "=f"(y) : "f"(x)); return y;
}
__device__ __forceinline__ float ex2a(float x) {
    float y; asm("ex2.approx.f32 %0,%1;" : "=f"(y) : "f"(x)); return y;
}
// y = (x <= 2) ? y : ex2(earg)   — predicated MUFU overwrite, no FSEL
__device__ __forceinline__ float sel_large(float y, float x, float earg) {
    asm("{\n\t.reg .pred p;\n\t"
        "setp.gt.f32 p,%1,0f40000000;\n\t"
        "@p ex2.approx.f32 %0,%2;\n\t}"
        : "+f"(y) : "f"(x), "f"(earg));
    return y;
}

__device__ __forceinline__ void k1_pair(float x0, float x1, float& y0, float& y1) {
    const ull x = f2(x0, x1);
    const ull r = f2(rcpa(x0), rcpa(x1));
    const ull L = f2(lg2a(x0), lg2a(x1));
    const ull s = fmul2(x, x);

    // P1(s): ln2 * I1_small refolded to s = x^2, economized deg 2
    ull p1 = dup(2.0408281e-3f);
    p1 = ffma2(p1, s, dup(4.2966284e-2f));
    p1 = ffma2(p1, s, dup(0.34665256f));

    // Q'(s) = Q(s) - P1(s); Q = (P2_exact(s) - 1)/s folded to deg 3
    ull q = dup(-8.3601954e-5f);
    q = ffma2(q, s, dup(-4.8562800e-3f));
    q = ffma2(q, s, dup(-8.5032647e-2f));
    q = ffma2(q, s, dup(-0.30804254f));

    // small = x*(L*P1 + Q') + r
    const ull inner = ffma2(L, p1, q);
    const ull small2 = ffma2(x, inner, r);

    // G(r) = log2(P3(r)), cubic fit on [0.099, 0.5]
    ull g = dup(0.077542f);
    g = ffma2(g, r, dup(-0.221725f));
    g = ffma2(g, r, dup(0.534130f));
    g = ffma2(g, r, dup(0.326080f));

    // earg = -log2e*x - 0.5*L + G
    const ull t = ffma2(L, dup(-0.5f), g);
    const ull earg = ffma2(x, dup(-1.44269504f), t);

    float e0, e1, s0, s1;
    unpack2(earg, e0, e1);
    unpack2(small2, s0, s1);
    y0 = sel_large(s0, x0, e0);
    y1 = sel_large(s1, x1, e1);
}

static constexpr int TPB = 256;
static constexpr int V = 2;  // float4s per thread

__global__ void __launch_bounds__(TPB, 8) k1_main(const float4* __restrict__ in,
                                                  float4* __restrict__ out) {
    int i = blockIdx.x * (TPB * V) + threadIdx.x;
    float4 v0 = __ldcs(&in[i]);
    float4 v1 = __ldcs(&in[i + TPB]);
    float4 o0, o1;
    k1_pair(v0.x, v0.y, o0.x, o0.y);
    k1_pair(v0.z, v0.w, o0.z, o0.w);
    __stcs(&out[i], o0);
    k1_pair(v1.x, v1.y, o1.x, o1.y);
    k1_pair(v1.z, v1.w, o1.z, o1.w);
    __stcs(&out[i + TPB], o1);
}

// Generic scalar tail for leftover elements (unused for 8192x8192).
__device__ __forceinline__ float k1_scalar(float x) {
    float r = rcpa(x), L = lg2a(x);
    float s = x * x;
    float p1 = 2.0408281e-3f;
    p1 = fmaf(p1, s, 4.2966284e-2f);
    p1 = fmaf(p1, s, 0.34665256f);
    float q = -8.3601954e-5f;
    q = fmaf(q, s, -4.8562800e-3f);
    q = fmaf(q, s, -8.5032647e-2f);
    q = fmaf(q, s, -0.30804254f);
    float small = fmaf(x, fmaf(L, p1, q), r);
    float g = 0.077542f;
    g = fmaf(g, r, -0.221725f);
    g = fmaf(g, r, 0.534130f);
    g = fmaf(g, r, 0.326080f);
    float large = ex2a(fmaf(x, -1.44269504f, fmaf(L, -0.5f, g)));
    return (x <= 2.0f) ? small : large;
}

__global__ void k1_tail(const float* __restrict__ in, float* __restrict__ out,
                        int start, int n) {
    int i = start + blockIdx.x * blockDim.x + threadIdx.x;
    if (i < n) out[i] = k1_scalar(in[i]);
}

extern "C" void kernel_launch(void* const* d_in, const int* in_sizes, int n_in,
                              void* d_out, int out_size) {
    const float* x = (const float*)d_in[0];
    float* y = (float*)d_out;
    int n = in_sizes[0];

    int elems_per_block = TPB * V * 4;                   // 2048 elements
    int full_blocks = n / elems_per_block;               // 32768 for 8192^2
    if (full_blocks > 0) {
        k1_main<<<full_blocks, TPB>>>((const float4*)x, (float4*)y);
    }
    int done = full_blocks * elems_per_block;
    int rem = n - done;
    if (rem > 0) {
        int blocks = (rem + 255) / 256;
        k1_tail<<<blocks, 256>>>(x, y, done, n);
    }
}

// round 12
// speedup vs baseline: 1.0004x; 1.0004x over previous
#include <cuda_runtime.h>

// Modified Bessel K1(x) on (0.1, 10.1], matching the JAX fp32 A&S reference.
// Math (R7 form, rel_err ~2e-5 vs 1e-3 budget):
//   small(x) = x*( L*P1(s) + Q'(s) ) + r          [x <= 2]
//       s = x^2, r = rcp(x), L = lg2(x)
//   large(x) = ex2( -log2e*x - 0.5*L + G(r) )     [x > 2]
// R10 = R7 flat-grid structure (V=2, TPB=256, block-interleaved addresses —
// R9 proved per-CTA chunking wrecks L2 behavior) + predicated-MUFU select:
// "@p ex2" overwrites the small result directly, killing FSETP+2xFSEL per
// pair (the alu pipe at 49% was the binder).

typedef unsigned long long ull;

__device__ __forceinline__ ull f2(float lo, float hi) {
    ull d; asm("mov.b64 %0,{%1,%2};" : "=l"(d) : "f"(lo), "f"(hi)); return d;
}
__device__ __forceinline__ ull dup(float c) { return f2(c, c); }
__device__ __forceinline__ void unpack2(ull v, float& lo, float& hi) {
    asm("mov.b64 {%0,%1},%2;" : "=f"(lo), "=f"(hi) : "l"(v));
}
__device__ __forceinline__ ull ffma2(ull a, ull b, ull c) {
    ull d; asm("fma.rn.f32x2 %0,%1,%2,%3;" : "=l"(d) : "l"(a), "l"(b), "l"(c)); return d;
}
__device__ __forceinline__ ull fmul2(ull a, ull b) {
    ull d; asm("mul.rn.f32x2 %0,%1,%2;" : "=l"(d) : "l"(a), "l"(b)); return d;
}
__device__ __forceinline__ float rcpa(float x) {
    float y; asm("rcp.approx.f32 %0,%1;" : "=f"(y) : "f"(x)); return y;
}
__device__ __forceinline__ float lg2a(float x) {
    float y; asm("lg2.approx.f32 %0,%1;" : "=f"(y) : "f"(x)); return y;
}
__device__ __forceinline__ float ex2a(float x) {
    float y; asm("ex2.approx.f32 %0,%1;" : "=f"(y) : "f"(x)); return y;
}
// y = (x <= 2) ? y : ex2(earg)   — predicated MUFU overwrite, no FSEL
__device__ __forceinline__ float sel_large(float y, float x, float earg) {
    asm("{\n\t.reg .pred p;\n\t"
        "setp.gt.f32 p,%1,0f40000000;\n\t"
        "@p ex2.approx.f32 %0,%2;\n\t}"
        : "+f"(y) : "f"(x), "f"(earg));
    return y;
}

__device__ __forceinline__ void k1_pair(float x0, float x1, float& y0, float& y1) {
    const ull x = f2(x0, x1);
    const ull r = f2(rcpa(x0), rcpa(x1));
    const ull L = f2(lg2a(x0), lg2a(x1));
    const ull s = fmul2(x, x);

    // P1(s): ln2 * I1_small refolded to s = x^2, economized deg 2
    ull p1 = dup(2.0408281e-3f);
    p1 = ffma2(p1, s, dup(4.2966284e-2f));
    p1 = ffma2(p1, s, dup(0.34665256f));

    // Q'(s) = Q(s) - P1(s); Q = (P2_exact(s) - 1)/s folded to deg 3
    ull q = dup(-8.3601954e-5f);
    q = ffma2(q, s, dup(-4.8562800e-3f));
    q = ffma2(q, s, dup(-8.5032647e-2f));
    q = ffma2(q, s, dup(-0.30804254f));

    // small = x*(L*P1 + Q') + r
    const ull inner = ffma2(L, p1, q);
    const ull small2 = ffma2(x, inner, r);

    // G(r) = log2(P3(r)), cubic fit on [0.099, 0.5]
    ull g = dup(0.077542f);
    g = ffma2(g, r, dup(-0.221725f));
    g = ffma2(g, r, dup(0.534130f));
    g = ffma2(g, r, dup(0.326080f));

    // earg = -log2e*x - 0.5*L + G
    const ull t = ffma2(L, dup(-0.5f), g);
    const ull earg = ffma2(x, dup(-1.44269504f), t);

    float e0, e1, s0, s1;
    unpack2(earg, e0, e1);
    unpack2(small2, s0, s1);
    y0 = sel_large(s0, x0, e0);
    y1 = sel_large(s1, x1, e1);
}

static constexpr int TPB = 256;
static constexpr int V = 2;  // float4s per thread

__global__ void __launch_bounds__(TPB, 8) k1_main(const float4* __restrict__ in,
                                                  float4* __restrict__ out) {
    int i = blockIdx.x * (TPB * V) + threadIdx.x;
    float4 v0 = __ldcs(&in[i]);
    float4 v1 = __ldcs(&in[i + TPB]);
    float4 o0, o1;
    k1_pair(v0.x, v0.y, o0.x, o0.y);
    k1_pair(v0.z, v0.w, o0.z, o0.w);
    __stcs(&out[i], o0);
    k1_pair(v1.x, v1.y, o1.x, o1.y);
    k1_pair(v1.z, v1.w, o1.z, o1.w);
    __stcs(&out[i + TPB], o1);
}

// Generic scalar tail for leftover elements (unused for 8192x8192).
__device__ __forceinline__ float k1_scalar(float x) {
    float r = rcpa(x), L = lg2a(x);
    float s = x * x;
    float p1 = 2.0408281e-3f;
    p1 = fmaf(p1, s, 4.2966284e-2f);
    p1 = fmaf(p1, s, 0.34665256f);
    float q = -8.3601954e-5f;
    q = fmaf(q, s, -4.8562800e-3f);
    q = fmaf(q, s, -8.5032647e-2f);
    q = fmaf(q, s, -0.30804254f);
    float small = fmaf(x, fmaf(L, p1, q), r);
    float g = 0.077542f;
    g = fmaf(g, r, -0.221725f);
    g = fmaf(g, r, 0.534130f);
    g = fmaf(g, r, 0.326080f);
    float large = ex2a(fmaf(x, -1.44269504f, fmaf(L, -0.5f, g)));
    return (x <= 2.0f) ? small : large;
}

__global__ void k1_tail(const float* __restrict__ in, float* __restrict__ out,
                        int start, int n) {
    int i = start + blockIdx.x * blockDim.x + threadIdx.x;
    if (i < n) out[i] = k1_scalar(in[i]);
}

extern "C" void kernel_launch(void* const* d_in, const int* in_sizes, int n_in,
                              void* d_out, int out_size) {
    const float* x = (const float*)d_in[0];
    float* y = (float*)d_out;
    int n = in_sizes[0];

    int elems_per_block = TPB * V * 4;                   // 2048 elements
    int full_blocks = n / elems_per_block;               // 32768 for 8192^2
    if (full_blocks > 0) {
        k1_main<<<full_blocks, TPB>>>((const float4*)x, (float4*)y);
    }
    int done = full_blocks * elems_per_block;
    int rem = n - done;
    if (rem > 0) {
        int blocks = (rem + 255) / 256;
        k1_tail<<<blocks, 256>>>(x, y, done, n);
    }
}

// round 13
// speedup vs baseline: 1.0083x; 1.0079x over previous
#include <cuda_runtime.h>

// Modified Bessel K1(x) on (0.1, 10.1], matching the JAX fp32 A&S reference.
// Math (R7 form, rel_err ~2e-5 vs 1e-3 budget):
//   small(x) = x*( L*P1(s) + Q'(s) ) + r          [x <= 2]
//       s = x^2, r = rcp(x), L = lg2(x)
//   large(x) = ex2( -log2e*x - 0.5*L + G(r) )     [x > 2]
// R10 = R7 flat-grid structure (V=2, TPB=256, block-interleaved addresses —
// R9 proved per-CTA chunking wrecks L2 behavior) + predicated-MUFU select:
// "@p ex2" overwrites the small result directly, killing FSETP+2xFSEL per
// pair (the alu pipe at 49% was the binder).

typedef unsigned long long ull;

__device__ __forceinline__ ull f2(float lo, float hi) {
    ull d; asm("mov.b64 %0,{%1,%2};" : "=l"(d) : "f"(lo), "f"(hi)); return d;
}
__device__ __forceinline__ ull dup(float c) { return f2(c, c); }
__device__ __forceinline__ void unpack2(ull v, float& lo, float& hi) {
    asm("mov.b64 {%0,%1},%2;" : "=f"(lo), "=f"(hi) : "l"(v));
}
__device__ __forceinline__ ull ffma2(ull a, ull b, ull c) {
    ull d; asm("fma.rn.f32x2 %0,%1,%2,%3;" : "=l"(d) : "l"(a), "l"(b), "l"(c)); return d;
}
__device__ __forceinline__ ull fmul2(ull a, ull b) {
    ull d; asm("mul.rn.f32x2 %0,%1,%2;" : "=l"(d) : "l"(a), "l"(b)); return d;
}
__device__ __forceinline__ float rcpa(float x) {
    float y; asm("rcp.approx.f32 %0,%1;" : "=f"(y) : "f"(x)); return y;
}
__device__ __forceinline__ float lg2a(float x) {
    float y; asm("lg2.approx.f32 %0,%1;" : "=f"(y) : "f"(x)); return y;
}
__device__ __forceinline__ float ex2a(float x) {
    float y; asm("ex2.approx.f32 %0,%1;" : "=f"(y) : "f"(x)); return y;
}
// y = (x <= 2) ? y : ex2(earg)   — predicated MUFU overwrite, no FSEL
__device__ __forceinline__ float sel_large(float y, float x, float earg) {
    asm("{\n\t.reg .pred p;\n\t"
        "setp.gt.f32 p,%1,0f40000000;\n\t"
        "@p ex2.approx.f32 %0,%2;\n\t}"
        : "+f"(y) : "f"(x), "f"(earg));
    return y;
}

__device__ __forceinline__ void k1_pair(float x0, float x1, float& y0, float& y1) {
    const ull x = f2(x0, x1);
    const ull r = f2(rcpa(x0), rcpa(x1));
    const ull L = f2(lg2a(x0), lg2a(x1));
    const ull s = fmul2(x, x);

    // P1(s): ln2 * I1_small refolded to s = x^2, economized deg 2
    ull p1 = dup(2.0408281e-3f);
    p1 = ffma2(p1, s, dup(4.2966284e-2f));
    p1 = ffma2(p1, s, dup(0.34665256f));

    // Q'(s) = Q(s) - P1(s); Q = (P2_exact(s) - 1)/s folded to deg 3
    ull q = dup(-8.3601954e-5f);
    q = ffma2(q, s, dup(-4.8562800e-3f));
    q = ffma2(q, s, dup(-8.5032647e-2f));
    q = ffma2(q, s, dup(-0.30804254f));

    // small = x*(L*P1 + Q') + r
    const ull inner = ffma2(L, p1, q);
    const ull small2 = ffma2(x, inner, r);

    // G(r) = log2(P3(r)), cubic fit on [0.099, 0.5]
    ull g = dup(0.077542f);
    g = ffma2(g, r, dup(-0.221725f));
    g = ffma2(g, r, dup(0.534130f));
    g = ffma2(g, r, dup(0.326080f));

    // earg = -log2e*x - 0.5*L + G
    const ull t = ffma2(L, dup(-0.5f), g);
    const ull earg = ffma2(x, dup(-1.44269504f), t);

    float e0, e1, s0, s1;
    unpack2(earg, e0, e1);
    unpack2(small2, s0, s1);
    y0 = sel_large(s0, x0, e0);
    y1 = sel_large(s1, x1, e1);
}

static constexpr int TPB = 256;
static constexpr int V = 2;  // float4s per thread

__global__ void __launch_bounds__(TPB, 8) k1_main(const float4* __restrict__ in,
                                                  float4* __restrict__ out) {
    int i = blockIdx.x * (TPB * V) + threadIdx.x;
    float4 v0 = __ldcs(&in[i]);
    float4 v1 = __ldcs(&in[i + TPB]);
    float4 o0, o1;
    k1_pair(v0.x, v0.y, o0.x, o0.y);
    k1_pair(v0.z, v0.w, o0.z, o0.w);
    __stcs(&out[i], o0);
    k1_pair(v1.x, v1.y, o1.x, o1.y);
    k1_pair(v1.z, v1.w, o1.z, o1.w);
    __stcs(&out[i + TPB], o1);
}

// Generic scalar tail for leftover elements (unused for 8192x8192).
__device__ __forceinline__ float k1_scalar(float x) {
    float r = rcpa(x), L = lg2a(x);
    float s = x * x;
    float p1 = 2.0408281e-3f;
    p1 = fmaf(p1, s, 4.2966284e-2f);
    p1 = fmaf(p1, s, 0.34665256f);
    float q = -8.3601954e-5f;
    q = fmaf(q, s, -4.8562800e-3f);
    q = fmaf(q, s, -8.5032647e-2f);
    q = fmaf(q, s, -0.30804254f);
    float small = fmaf(x, fmaf(L, p1, q), r);
    float g = 0.077542f;
    g = fmaf(g, r, -0.221725f);
    g = fmaf(g, r, 0.534130f);
    g = fmaf(g, r, 0.326080f);
    float large = ex2a(fmaf(x, -1.44269504f, fmaf(L, -0.5f, g)));
    return (x <= 2.0f) ? small : large;
}

__global__ void k1_tail(const float* __restrict__ in, float* __restrict__ out,
                        int start, int n) {
    int i = start + blockIdx.x * blockDim.x + threadIdx.x;
    if (i < n) out[i] = k1_scalar(in[i]);
}

extern "C" void kernel_launch(void* const* d_in, const int* in_sizes, int n_in,
                              void* d_out, int out_size) {
    const float* x = (const float*)d_in[0];
    float* y = (float*)d_out;
    int n = in_sizes[0];

    int elems_per_block = TPB * V * 4;                   // 2048 elements
    int full_blocks = n / elems_per_block;               // 32768 for 8192^2
    if (full_blocks > 0) {
        k1_main<<<full_blocks, TPB>>>((const float4*)x, (float4*)y);
    }
    int done = full_blocks * elems_per_block;
    int rem = n - done;
    if (rem > 0) {
        int blocks = (rem + 255) / 256;
        k1_tail<<<blocks, 256>>>(x, y, done, n);
    }
}